// round 12
// baseline (speedup 1.0000x reference)
#include <cuda_runtime.h>
#include <math.h>

#define NFR 5
#define BB  8
#define CC  64
#define HW  16384
#define KK  320
#define TPX 64             // pixels per fused block
#define GX  (HW/TPX)       // 256 blocks per batch

#define WSTR 72            // wbuf row stride (A-frag loads conflict-free)
#define XS_FLOATS   (KK*TPX)          // 20480 (no padding; XOR swizzle)
#define WBUF_FLOATS (2*32*WSTR)       // 4608
#define SRED_FLOATS (2*768)           // 1536
#define SMEM_BYTES  ((XS_FLOATS+WBUF_FLOATS+SRED_FLOATS)*4)   // 106496 -> 2 CTA/SM

__device__ float g_wt[KK*CC];                      // transposed W: [k][c]
__device__ float g_part[(size_t)BB*GX*768];
__device__ float g_A[BB*NFR*CC];

__device__ __forceinline__ void cp16(void* s, const void* g){
    unsigned saddr = (unsigned)__cvta_generic_to_shared(s);
    asm volatile("cp.async.cg.shared.global [%0], [%1], 16;\n" :: "r"(saddr), "l"(g) : "memory");
}
__device__ __forceinline__ void cp_commit(){ asm volatile("cp.async.commit_group;\n" ::: "memory"); }
__device__ __forceinline__ void cp_wait_n(int n){
    switch (n) {
        case 0: asm volatile("cp.async.wait_group 0;" ::: "memory"); break;
        case 1: asm volatile("cp.async.wait_group 1;" ::: "memory"); break;
        case 2: asm volatile("cp.async.wait_group 2;" ::: "memory"); break;
        case 3: asm volatile("cp.async.wait_group 3;" ::: "memory"); break;
        case 4: asm volatile("cp.async.wait_group 4;" ::: "memory"); break;
        case 5: asm volatile("cp.async.wait_group 5;" ::: "memory"); break;
        case 6: asm volatile("cp.async.wait_group 6;" ::: "memory"); break;
        case 7: asm volatile("cp.async.wait_group 7;" ::: "memory"); break;
        case 8: asm volatile("cp.async.wait_group 8;" ::: "memory"); break;
        default: asm volatile("cp.async.wait_group 9;" ::: "memory"); break;
    }
}

__device__ __forceinline__ void mma_tf32(float c[4], unsigned a0, unsigned a1, unsigned a2,
                                         unsigned a3, unsigned b0, unsigned b1) {
    asm volatile("mma.sync.aligned.m16n8k8.row.col.f32.tf32.tf32.f32 "
                 "{%0,%1,%2,%3}, {%4,%5,%6,%7}, {%8,%9}, {%0,%1,%2,%3};"
                 : "+f"(c[0]), "+f"(c[1]), "+f"(c[2]), "+f"(c[3])
                 : "r"(a0), "r"(a1), "r"(a2), "r"(a3), "r"(b0), "r"(b1));
}

// ---------------------------------------------------------------------------
// W transpose split into two launches (launch-order instrumentation so the
// fused kernel lands at launch #4 for the ncu capture window).
// ---------------------------------------------------------------------------
__global__ __launch_bounds__(256) void k_wt_a(const float* __restrict__ w) {
    int i = blockIdx.x * 256 + threadIdx.x;      // i = k*64 + c, k < 160
    int k = i >> 6, c = i & 63;
    g_wt[i] = w[c * KK + k];
}
__global__ __launch_bounds__(256) void k_wt_b(const float* __restrict__ w) {
    int i = (KK * CC / 2) + blockIdx.x * 256 + threadIdx.x;
    int k = i >> 6, c = i & 63;
    g_wt[i] = w[c * KK + k];
}
// Trivial launch #3 (g_part is fully overwritten by the fused kernel).
__global__ void k_pad() {
    g_part[threadIdx.x] = 0.f;
}

// ---------------------------------------------------------------------------
// Fused origin GEMM (tf32 MMA) + difference-basis stats. (unchanged from R9)
// ---------------------------------------------------------------------------
__global__ __launch_bounds__(256, 2) void k_origin_fused(const float* __restrict__ inp) {
    extern __shared__ float sm[];
    float* xs   = sm;                              // [320][64] swizzled
    float* wbuf = sm + XS_FLOATS;                  // [2][32][WSTR]
    float* sred = sm + XS_FLOATS + WBUF_FLOATS;    // [2][768]

    const int tid  = threadIdx.x;
    const int b    = blockIdx.y, bx = blockIdx.x;
    const int p0   = bx * TPX;
    const int wid  = tid >> 5, lane = tid & 31;
    const int gid  = lane >> 2, tig = lane & 3;
    const int wm   = wid >> 1, wn = wid & 1;
    const int c0   = wm * 16, pb = wn * 32;
    const int krW  = tid >> 3;
    const int c8   = (tid & 7) * 8;

    float cf[4][4];
#pragma unroll
    for (int j = 0; j < 4; j++)
#pragma unroll
        for (int i = 0; i < 4; i++) cf[j][i] = 0.f;

    int boff[4];
#pragma unroll
    for (int j = 0; j < 4; j++) {
        int p = pb + 8 * j + gid;
        boff[j] = ((((p >> 2) ^ (tig << 1)) << 2) + (p & 3));
    }

    // prologue: issue ALL X chunk loads as 10 commit groups
#pragma unroll
    for (int ch = 0; ch < 10; ch++) {
#pragma unroll
        for (int it = 0; it < 2; it++) {
            int e = it * 256 + tid;
            int row = e >> 4, col4 = e & 15;
            int k = ch * 32 + row;
            int unit = col4 ^ ((k & 3) << 1);
            int f = k >> 6, cp = k & 63;
            cp16(xs + k * TPX + unit * 4,
                 inp + (size_t)((f * BB + b) * CC + cp) * HW + p0 + col4 * 4);
        }
        cp_commit();
    }

    {
        float4 wa = *(const float4*)(g_wt + krW * 64 + c8);
        float4 wb4 = *(const float4*)(g_wt + krW * 64 + c8 + 4);
        *(float4*)(wbuf + krW * WSTR + c8)     = wa;
        *(float4*)(wbuf + krW * WSTR + c8 + 4) = wb4;
    }
    cp_wait_n(9);
    __syncthreads();

#pragma unroll
    for (int ch = 0; ch < 10; ch++) {
        float4 wna, wnb;
        if (ch < 9) {
            const float* wsrc = g_wt + (ch + 1) * 32 * 64 + krW * 64 + c8;
            wna = *(const float4*)(wsrc);
            wnb = *(const float4*)(wsrc + 4);
        }

        const float* wb = wbuf + (ch & 1) * (32 * WSTR);
        const int kg = ch * 32;
#pragma unroll
        for (int ks = 0; ks < 4; ks++) {
            const int kk = ks * 8;
            unsigned a0 = __float_as_uint(wb[(kk + tig) * WSTR + c0 + gid]);
            unsigned a1 = __float_as_uint(wb[(kk + tig) * WSTR + c0 + gid + 8]);
            unsigned a2 = __float_as_uint(wb[(kk + tig + 4) * WSTR + c0 + gid]);
            unsigned a3 = __float_as_uint(wb[(kk + tig + 4) * WSTR + c0 + gid + 8]);
            const float* xr0 = xs + (kg + kk + tig) * TPX;
            const float* xr1 = xr0 + 4 * TPX;
#pragma unroll
            for (int j = 0; j < 4; j++) {
                unsigned b0 = __float_as_uint(xr0[boff[j]]);
                unsigned b1 = __float_as_uint(xr1[boff[j]]);
                mma_tf32(cf[j], a0, a1, a2, a3, b0, b1);
            }
        }

        if (ch < 9) {
            float* wd = wbuf + ((ch + 1) & 1) * (32 * WSTR);
            *(float4*)(wd + krW * WSTR + c8)     = wna;
            *(float4*)(wd + krW * WSTR + c8 + 4) = wnb;
            cp_wait_n(8 - ch);
        }
        __syncthreads();
    }

    // fused stats epilogue
    int eoff[4];
#pragma unroll
    for (int j = 0; j < 4; j++) {
        int p = pb + 8 * j + 2 * tig;
        eoff[j] = ((((p >> 2) ^ ((gid & 3) << 1)) << 2) + (p & 3));
    }

#pragma unroll
    for (int rr = 0; rr < 2; rr++) {
        const int r = c0 + gid + rr * 8;
        const float* lr = xs + (4 * CC + r) * TPX;
        float dt[4] = {0,0,0,0}, nr[4] = {0,0,0,0}, ds[4] = {0,0,0,0};
#pragma unroll
        for (int j = 0; j < 4; j++) {
            float2 l = *(const float2*)(lr + eoff[j]);
            float o0 = cf[j][rr * 2 + 0];
            float o1 = cf[j][rr * 2 + 1];
#pragma unroll
            for (int f = 0; f < 4; f++) {
                float2 xf = *(const float2*)(xs + (f * CC + r) * TPX + eoff[j]);
                float d0 = l.x - xf.x, d1 = l.y - xf.y;
                dt[f] += o0 * d0 + o1 * d1;
                nr[f] += d0 * d0 + d1 * d1;
                ds[f] += d0 + d1;
            }
        }
#pragma unroll
        for (int f = 0; f < 4; f++) {
            dt[f] += __shfl_xor_sync(0xffffffffu, dt[f], 1);
            dt[f] += __shfl_xor_sync(0xffffffffu, dt[f], 2);
            nr[f] += __shfl_xor_sync(0xffffffffu, nr[f], 1);
            nr[f] += __shfl_xor_sync(0xffffffffu, nr[f], 2);
            ds[f] += __shfl_xor_sync(0xffffffffu, ds[f], 1);
            ds[f] += __shfl_xor_sync(0xffffffffu, ds[f], 2);
        }
        if (tig == 0) {
            float* dp = sred + wn * 768 + r * 12;
#pragma unroll
            for (int f = 0; f < 4; f++) { dp[f] = dt[f]; dp[4 + f] = nr[f]; dp[8 + f] = ds[f]; }
        }
    }
    __syncthreads();

    float* gp = g_part + (size_t)(b * GX + bx) * 768;
    for (int i = tid; i < 768; i += 256)
        gp[i] = sred[i] + sred[768 + i];
}

// ---------------------------------------------------------------------------
// Reduce 256 block-partials per (b,c), compute coefficients, fold weights.
// ---------------------------------------------------------------------------
__global__ __launch_bounds__(256) void k_reduce_coef(const float* __restrict__ origin_b,
                                                     const float* __restrict__ out_w) {
    const int c = blockIdx.x, b = blockIdx.y, tid = threadIdx.x;
    const float4* gp = (const float4*)(g_part + (size_t)(b * GX + tid) * 768 + c * 12);
    float4 a0 = gp[0], a1 = gp[1], a2 = gp[2];
    float v[12] = {a0.x,a0.y,a0.z,a0.w, a1.x,a1.y,a1.z,a1.w, a2.x,a2.y,a2.z,a2.w};

    const int lane = tid & 31, wrp = tid >> 5;
#pragma unroll
    for (int s = 0; s < 12; s++)
#pragma unroll
        for (int off = 16; off; off >>= 1)
            v[s] += __shfl_down_sync(0xffffffffu, v[s], off);

    __shared__ float red[8][12];
    if (lane == 0) {
#pragma unroll
        for (int s = 0; s < 12; s++) red[wrp][s] = v[s];
    }
    __syncthreads();

    if (tid == 0) {
        float st[12];
#pragma unroll
        for (int s = 0; s < 12; s++) {
            float t = 0.f;
#pragma unroll
            for (int w = 0; w < 8; w++) t += red[w][s];
            st[s] = t;
        }
        float w1 = out_w[c], w2 = out_w[CC + c], ob = origin_b[c];
        float ssum = 0.f;
#pragma unroll
        for (int f = 0; f < 4; f++) {
            float dtot = st[f] + ob * st[8 + f];
            float den  = fmaxf(sqrtf(st[4 + f]), 1e-12f);
            float coef = dtot / (den * den);
            g_A[(b * NFR + f) * CC + c] = -w1 * coef;
            ssum += coef;
        }
        g_A[(b * NFR + 4) * CC + c] = w2 + w1 * ssum;
    }
}

// ---------------------------------------------------------------------------
// Unified final GEMV: y[b,p] = sum_{k<320} A[b,k]*inp[k,b,p] + ob.
// No g_yp round-trip, no combine kernel. grid (HW/512, B) reversed for L2
// reuse of the fused kernel's tail; forced MLP=8 float4 batches.
// ---------------------------------------------------------------------------
__global__ __launch_bounds__(128) void k_final(const float* __restrict__ inp,
                                               const float* __restrict__ out_b,
                                               float* __restrict__ y) {
    __shared__ float sA[KK];
    const int b = blockIdx.y, tid = threadIdx.x;
    for (int i = tid; i < KK; i += 128) sA[i] = g_A[b * KK + i];   // [f][c] contiguous
    __syncthreads();

    const int bxr = gridDim.x - 1 - blockIdx.x;     // reversed pixel order
    const int p = bxr * 512 + tid * 4;
    float ob = out_b[0];
    float4 acc = make_float4(ob, ob, ob, ob);
    for (int k = 0; k < KK; k += 8) {
        float4 v[8];
#pragma unroll
        for (int i = 0; i < 8; i++) {
            int kk = k + i;
            int f = kk >> 6, c = kk & 63;
            v[i] = *(const float4*)(inp + (size_t)((f * BB + b) * CC + c) * HW + p);
        }
#pragma unroll
        for (int i = 0; i < 8; i++) {
            float a = sA[k + i];
            acc.x += a * v[i].x; acc.y += a * v[i].y;
            acc.z += a * v[i].z; acc.w += a * v[i].w;
        }
    }
    *(float4*)(y + (size_t)b * HW + p) = acc;
}

// ---------------------------------------------------------------------------
extern "C" void kernel_launch(void* const* d_in, const int* in_sizes, int n_in,
                              void* d_out, int out_size) {
    const float* inp      = (const float*)d_in[0];
    const float* origin_w = (const float*)d_in[1];
    const float* origin_b = (const float*)d_in[2];
    const float* out_w    = (const float*)d_in[3];
    const float* out_b    = (const float*)d_in[4];
    float* y = (float*)d_out;

    static int inited = 0;
    if (!inited) {
        cudaFuncSetAttribute(k_origin_fused, cudaFuncAttributeMaxDynamicSharedMemorySize, SMEM_BYTES);
        inited = 1;
    }

    k_wt_a        <<<KK * CC / 512, 256>>>(origin_w);           // launch 1
    k_wt_b        <<<KK * CC / 512, 256>>>(origin_w);           // launch 2
    k_pad         <<<1, 32>>>();                                // launch 3
    k_origin_fused<<<dim3(GX, BB), 256, SMEM_BYTES>>>(inp);     // launch 4 (profiled)
    k_reduce_coef <<<dim3(CC, BB), 256>>>(origin_b, out_w);     // launch 5
    k_final       <<<dim3(HW / 512, BB), 128>>>(inp, out_b, y); // launch 6
}

// round 14
// speedup vs baseline: 1.1954x; 1.1954x over previous
#include <cuda_runtime.h>
#include <math.h>

#define NFR 5
#define BB  8
#define CC  64
#define HW  16384
#define KK  320
#define TPX 64             // pixels per fused block
#define GX  (HW/TPX)       // 256 blocks per batch

#define WSTR 72            // wbuf row stride (A-frag loads conflict-free)
#define XS_FLOATS   (KK*TPX)          // 20480 (no padding; XOR swizzle)
#define WBUF_FLOATS (2*32*WSTR)       // 4608
#define SRED_FLOATS (2*768)           // 1536
#define SMEM_BYTES  ((XS_FLOATS+WBUF_FLOATS+SRED_FLOATS)*4)   // 106496 -> 2 CTA/SM

__device__ float g_wt[KK*CC];                      // transposed W: [k][c]
__device__ float g_part[(size_t)BB*GX*768];
__device__ float g_A[BB*NFR*CC];

__device__ __forceinline__ void cp16(void* s, const void* g){
    unsigned saddr = (unsigned)__cvta_generic_to_shared(s);
    asm volatile("cp.async.cg.shared.global [%0], [%1], 16;\n" :: "r"(saddr), "l"(g) : "memory");
}
__device__ __forceinline__ void cp_commit(){ asm volatile("cp.async.commit_group;\n" ::: "memory"); }
__device__ __forceinline__ void cp_wait_n(int n){
    switch (n) {
        case 0: asm volatile("cp.async.wait_group 0;" ::: "memory"); break;
        case 1: asm volatile("cp.async.wait_group 1;" ::: "memory"); break;
        case 2: asm volatile("cp.async.wait_group 2;" ::: "memory"); break;
        case 3: asm volatile("cp.async.wait_group 3;" ::: "memory"); break;
        case 4: asm volatile("cp.async.wait_group 4;" ::: "memory"); break;
        case 5: asm volatile("cp.async.wait_group 5;" ::: "memory"); break;
        case 6: asm volatile("cp.async.wait_group 6;" ::: "memory"); break;
        case 7: asm volatile("cp.async.wait_group 7;" ::: "memory"); break;
        case 8: asm volatile("cp.async.wait_group 8;" ::: "memory"); break;
        default: asm volatile("cp.async.wait_group 9;" ::: "memory"); break;
    }
}

__device__ __forceinline__ void mma_tf32(float c[4], unsigned a0, unsigned a1, unsigned a2,
                                         unsigned a3, unsigned b0, unsigned b1) {
    asm volatile("mma.sync.aligned.m16n8k8.row.col.f32.tf32.tf32.f32 "
                 "{%0,%1,%2,%3}, {%4,%5,%6,%7}, {%8,%9}, {%0,%1,%2,%3};"
                 : "+f"(c[0]), "+f"(c[1]), "+f"(c[2]), "+f"(c[3])
                 : "r"(a0), "r"(a1), "r"(a2), "r"(a3), "r"(b0), "r"(b1));
}

// ---------------------------------------------------------------------------
// W transpose: g_wt[k*64+c] = origin_w[c*320+k].
// ---------------------------------------------------------------------------
__global__ __launch_bounds__(256) void k_wt(const float* __restrict__ w) {
    int i = blockIdx.x * 256 + threadIdx.x;      // i = k*64 + c
    int k = i >> 6, c = i & 63;
    g_wt[i] = w[c * KK + k];
}

// ---------------------------------------------------------------------------
// Fused origin GEMM (tf32 MMA) + difference-basis stats. (proven R9 version)
// ---------------------------------------------------------------------------
__global__ __launch_bounds__(256, 2) void k_origin_fused(const float* __restrict__ inp) {
    extern __shared__ float sm[];
    float* xs   = sm;                              // [320][64] swizzled
    float* wbuf = sm + XS_FLOATS;                  // [2][32][WSTR]
    float* sred = sm + XS_FLOATS + WBUF_FLOATS;    // [2][768]

    const int tid  = threadIdx.x;
    const int b    = blockIdx.y, bx = blockIdx.x;
    const int p0   = bx * TPX;
    const int wid  = tid >> 5, lane = tid & 31;
    const int gid  = lane >> 2, tig = lane & 3;
    const int wm   = wid >> 1, wn = wid & 1;
    const int c0   = wm * 16, pb = wn * 32;
    const int krW  = tid >> 3;
    const int c8   = (tid & 7) * 8;

    float cf[4][4];
#pragma unroll
    for (int j = 0; j < 4; j++)
#pragma unroll
        for (int i = 0; i < 4; i++) cf[j][i] = 0.f;

    int boff[4];
#pragma unroll
    for (int j = 0; j < 4; j++) {
        int p = pb + 8 * j + gid;
        boff[j] = ((((p >> 2) ^ (tig << 1)) << 2) + (p & 3));
    }

    // prologue: issue ALL X chunk loads as 10 commit groups (xs persistent)
#pragma unroll
    for (int ch = 0; ch < 10; ch++) {
#pragma unroll
        for (int it = 0; it < 2; it++) {
            int e = it * 256 + tid;
            int row = e >> 4, col4 = e & 15;
            int k = ch * 32 + row;
            int unit = col4 ^ ((k & 3) << 1);
            int f = k >> 6, cp = k & 63;
            cp16(xs + k * TPX + unit * 4,
                 inp + (size_t)((f * BB + b) * CC + cp) * HW + p0 + col4 * 4);
        }
        cp_commit();
    }

    {
        float4 wa = *(const float4*)(g_wt + krW * 64 + c8);
        float4 wb4 = *(const float4*)(g_wt + krW * 64 + c8 + 4);
        *(float4*)(wbuf + krW * WSTR + c8)     = wa;
        *(float4*)(wbuf + krW * WSTR + c8 + 4) = wb4;
    }
    cp_wait_n(9);
    __syncthreads();

#pragma unroll
    for (int ch = 0; ch < 10; ch++) {
        float4 wna, wnb;
        if (ch < 9) {
            const float* wsrc = g_wt + (ch + 1) * 32 * 64 + krW * 64 + c8;
            wna = *(const float4*)(wsrc);
            wnb = *(const float4*)(wsrc + 4);
        }

        const float* wb = wbuf + (ch & 1) * (32 * WSTR);
        const int kg = ch * 32;
#pragma unroll
        for (int ks = 0; ks < 4; ks++) {
            const int kk = ks * 8;
            unsigned a0 = __float_as_uint(wb[(kk + tig) * WSTR + c0 + gid]);
            unsigned a1 = __float_as_uint(wb[(kk + tig) * WSTR + c0 + gid + 8]);
            unsigned a2 = __float_as_uint(wb[(kk + tig + 4) * WSTR + c0 + gid]);
            unsigned a3 = __float_as_uint(wb[(kk + tig + 4) * WSTR + c0 + gid + 8]);
            const float* xr0 = xs + (kg + kk + tig) * TPX;
            const float* xr1 = xr0 + 4 * TPX;
#pragma unroll
            for (int j = 0; j < 4; j++) {
                unsigned b0 = __float_as_uint(xr0[boff[j]]);
                unsigned b1 = __float_as_uint(xr1[boff[j]]);
                mma_tf32(cf[j], a0, a1, a2, a3, b0, b1);
            }
        }

        if (ch < 9) {
            float* wd = wbuf + ((ch + 1) & 1) * (32 * WSTR);
            *(float4*)(wd + krW * WSTR + c8)     = wna;
            *(float4*)(wd + krW * WSTR + c8 + 4) = wnb;
            cp_wait_n(8 - ch);
        }
        __syncthreads();
    }

    // fused stats epilogue
    int eoff[4];
#pragma unroll
    for (int j = 0; j < 4; j++) {
        int p = pb + 8 * j + 2 * tig;
        eoff[j] = ((((p >> 2) ^ ((gid & 3) << 1)) << 2) + (p & 3));
    }

#pragma unroll
    for (int rr = 0; rr < 2; rr++) {
        const int r = c0 + gid + rr * 8;
        const float* lr = xs + (4 * CC + r) * TPX;
        float dt[4] = {0,0,0,0}, nr[4] = {0,0,0,0}, ds[4] = {0,0,0,0};
#pragma unroll
        for (int j = 0; j < 4; j++) {
            float2 l = *(const float2*)(lr + eoff[j]);
            float o0 = cf[j][rr * 2 + 0];
            float o1 = cf[j][rr * 2 + 1];
#pragma unroll
            for (int f = 0; f < 4; f++) {
                float2 xf = *(const float2*)(xs + (f * CC + r) * TPX + eoff[j]);
                float d0 = l.x - xf.x, d1 = l.y - xf.y;
                dt[f] += o0 * d0 + o1 * d1;
                nr[f] += d0 * d0 + d1 * d1;
                ds[f] += d0 + d1;
            }
        }
#pragma unroll
        for (int f = 0; f < 4; f++) {
            dt[f] += __shfl_xor_sync(0xffffffffu, dt[f], 1);
            dt[f] += __shfl_xor_sync(0xffffffffu, dt[f], 2);
            nr[f] += __shfl_xor_sync(0xffffffffu, nr[f], 1);
            nr[f] += __shfl_xor_sync(0xffffffffu, nr[f], 2);
            ds[f] += __shfl_xor_sync(0xffffffffu, ds[f], 1);
            ds[f] += __shfl_xor_sync(0xffffffffu, ds[f], 2);
        }
        if (tig == 0) {
            float* dp = sred + wn * 768 + r * 12;
#pragma unroll
            for (int f = 0; f < 4; f++) { dp[f] = dt[f]; dp[4 + f] = nr[f]; dp[8 + f] = ds[f]; }
        }
    }
    __syncthreads();

    float* gp = g_part + (size_t)(b * GX + bx) * 768;
    for (int i = tid; i < 768; i += 256)
        gp[i] = sred[i] + sred[768 + i];
}

// ---------------------------------------------------------------------------
// Reduce 256 block-partials per (b,c), compute coefficients, fold weights.
// ---------------------------------------------------------------------------
__global__ __launch_bounds__(256) void k_reduce_coef(const float* __restrict__ origin_b,
                                                     const float* __restrict__ out_w) {
    const int c = blockIdx.x, b = blockIdx.y, tid = threadIdx.x;
    const float4* gp = (const float4*)(g_part + (size_t)(b * GX + tid) * 768 + c * 12);
    float4 a0 = gp[0], a1 = gp[1], a2 = gp[2];
    float v[12] = {a0.x,a0.y,a0.z,a0.w, a1.x,a1.y,a1.z,a1.w, a2.x,a2.y,a2.z,a2.w};

    const int lane = tid & 31, wrp = tid >> 5;
#pragma unroll
    for (int s = 0; s < 12; s++)
#pragma unroll
        for (int off = 16; off; off >>= 1)
            v[s] += __shfl_down_sync(0xffffffffu, v[s], off);

    __shared__ float red[8][12];
    if (lane == 0) {
#pragma unroll
        for (int s = 0; s < 12; s++) red[wrp][s] = v[s];
    }
    __syncthreads();

    if (tid == 0) {
        float st[12];
#pragma unroll
        for (int s = 0; s < 12; s++) {
            float t = 0.f;
#pragma unroll
            for (int w = 0; w < 8; w++) t += red[w][s];
            st[s] = t;
        }
        float w1 = out_w[c], w2 = out_w[CC + c], ob = origin_b[c];
        float ssum = 0.f;
#pragma unroll
        for (int f = 0; f < 4; f++) {
            float dtot = st[f] + ob * st[8 + f];
            float den  = fmaxf(sqrtf(st[4 + f]), 1e-12f);
            float coef = dtot / (den * den);
            g_A[(b * NFR + f) * CC + c] = -w1 * coef;
            ssum += coef;
        }
        g_A[(b * NFR + 4) * CC + c] = w2 + w1 * ssum;
    }
}

// ---------------------------------------------------------------------------
// Unified final GEMV, single pass, no g_yp round-trip:
//   y[b,p] = sum_{k<320} A[b,k] * inp[k,b,p] + ob
// grid (HW/256, B) = 512 blocks x 128 threads; 2 px (float2) per thread;
// forced MLP=8 LDG.64 batches -> DRAM-bound (~24us), not latency-bound.
// ---------------------------------------------------------------------------
__global__ __launch_bounds__(128) void k_final(const float* __restrict__ inp,
                                               const float* __restrict__ out_b,
                                               float* __restrict__ y) {
    __shared__ float sA[KK];
    const int b = blockIdx.y, tid = threadIdx.x;
    for (int i = tid; i < KK; i += 128) sA[i] = g_A[b * KK + i];
    __syncthreads();

    const int p = blockIdx.x * 256 + tid * 2;
    float ob = out_b[0];
    float2 acc = make_float2(ob, ob);
    const float* base = inp + (size_t)b * CC * HW + p;   // k=0 row (f=0,c=0)
    for (int k = 0; k < KK; k += 8) {
        float2 v[8];
#pragma unroll
        for (int i = 0; i < 8; i++) {
            int kk = k + i;
            int f = kk >> 6, c = kk & 63;
            v[i] = *(const float2*)(base + ((size_t)f * BB * CC + c) * HW);
        }
#pragma unroll
        for (int i = 0; i < 8; i++) {
            float a = sA[k + i];
            acc.x += a * v[i].x;
            acc.y += a * v[i].y;
        }
    }
    *(float2*)(y + (size_t)b * HW + p) = acc;
}

// ---------------------------------------------------------------------------
extern "C" void kernel_launch(void* const* d_in, const int* in_sizes, int n_in,
                              void* d_out, int out_size) {
    const float* inp      = (const float*)d_in[0];
    const float* origin_w = (const float*)d_in[1];
    const float* origin_b = (const float*)d_in[2];
    const float* out_w    = (const float*)d_in[3];
    const float* out_b    = (const float*)d_in[4];
    float* y = (float*)d_out;

    static int inited = 0;
    if (!inited) {
        cudaFuncSetAttribute(k_origin_fused, cudaFuncAttributeMaxDynamicSharedMemorySize, SMEM_BYTES);
        inited = 1;
    }

    k_wt          <<<KK * CC / 256, 256>>>(origin_w);
    k_origin_fused<<<dim3(GX, BB), 256, SMEM_BYTES>>>(inp);
    k_reduce_coef <<<dim3(CC, BB), 256>>>(origin_b, out_w);
    k_final       <<<dim3(HW / 256, BB), 128>>>(inp, out_b, y);
}